// round 11
// baseline (speedup 1.0000x reference)
#include <cuda_runtime.h>
#include <cuda_bf16.h>
#include <stdint.h>

// out[token, :] = sign(weight[id, :]) * max(scales[id, col/128], 1e-8)
// ids: int32 [16384], weight: f32 [50257,1024], scales: f32 [50257,8]
//
// Warp-private cp.async pipeline (best-wall design), occupancy-doubled:
// RPW halved 8->4 so grid doubles to 1024 -> ~6 resident blocks/SM (the
// 33KB-smem limit) instead of ~3.5, doubling warps feeding the DRAM write
// stream. Load depth per SM unchanged (~192KB in flight).

#define DIM       1024
#define NGROUP    8
#define THREADS   128
#define NW        4          // warps per block
#define DEPTH     2          // pipeline stages per warp
#define RPW       4          // rows (tokens) per warp
#define TPB       (NW * RPW) // 16 tokens per block -> grid 1024

__global__ __launch_bounds__(THREADS)
void literati_embed_kernel(const int* __restrict__ ids,
                           const float* __restrict__ weight,
                           const float* __restrict__ scales,
                           float* __restrict__ out)
{
    __shared__ __align__(16) float wbuf[NW][DEPTH][DIM];     // 32 KB
    __shared__ __align__(16) float sbuf[NW][DEPTH][NGROUP];  // 256 B
    __shared__ int srows[TPB];

    const int t    = threadIdx.x;
    const int wid  = t >> 5;
    const int ln   = t & 31;
    const int tok0 = blockIdx.x * TPB;

    if (t < TPB)
        srows[t] = ids[tok0 + t];
    __syncthreads();  // only block-wide sync

    auto issue = [&](int r) {
        if (r < RPW) {
            const int stage = r & (DEPTH - 1);
            const int row   = srows[wid * RPW + r];
            const float* src = weight + (size_t)row * DIM;
#pragma unroll
            for (int j = 0; j < 8; j++) {
                uint32_t dst = (uint32_t)__cvta_generic_to_shared(
                    &wbuf[wid][stage][j * 128 + ln * 4]);
                asm volatile("cp.async.cg.shared.global [%0], [%1], 16;\n"
                             :: "r"(dst), "l"(src + j * 128 + ln * 4));
            }
            if (ln < 2) {
                uint32_t dst = (uint32_t)__cvta_generic_to_shared(
                    &sbuf[wid][stage][ln * 4]);
                asm volatile("cp.async.cg.shared.global [%0], [%1], 16;\n"
                             :: "r"(dst), "l"(scales + (size_t)row * NGROUP + ln * 4));
            }
        }
        asm volatile("cp.async.commit_group;\n");
    };

#pragma unroll
    for (int r = 0; r < DEPTH; r++) issue(r);

    for (int r = 0; r < RPW; r++) {
        asm volatile("cp.async.wait_group %0;\n" :: "n"(DEPTH - 1));
        __syncwarp();

        const int stage = r & (DEPTH - 1);
        const int tok   = tok0 + wid * RPW + r;
        float4* orow = reinterpret_cast<float4*>(out + (size_t)tok * DIM);

#pragma unroll
        for (int j = 0; j < 8; j++) {
            float s = fmaxf(sbuf[wid][stage][j], 1e-8f);  // broadcast
            float4 w = *reinterpret_cast<const float4*>(
                &wbuf[wid][stage][j * 128 + ln * 4]);
            float4 o;
            o.x = (w.x < 0.0f) ? -s : s;
            o.y = (w.y < 0.0f) ? -s : s;
            o.z = (w.z < 0.0f) ? -s : s;
            o.w = (w.w < 0.0f) ? -s : s;
            __stcs(&orow[j * 32 + ln], o);
        }

        __syncwarp();
        issue(r + DEPTH);
    }
}

extern "C" void kernel_launch(void* const* d_in, const int* in_sizes, int n_in,
                              void* d_out, int out_size)
{
    const int* ids      = (const int*)d_in[0];
    const float* weight = (const float*)d_in[1];
    const float* scales = (const float*)d_in[2];
    float* out          = (float*)d_out;

    const int n_tokens = in_sizes[0];  // 16384, divisible by TPB
    const int blocks = n_tokens / TPB;

    literati_embed_kernel<<<blocks, THREADS>>>(ids, weight, scales, out);
}